// round 12
// baseline (speedup 1.0000x reference)
#include <cuda_runtime.h>
#include <cuda_fp16.h>
#include <cuda_fp8.h>
#include <cstdint>

// ---------------- Problem constants (fixed-shape bench) ----------------
#define T_MAX   8192
#define K_DIM   4096
#define O_DIM   4096
#define FP8_MAX 448.0f

// ---------------- Tensor GEMM tiling (R3 config, proven) ----------------
#define BM 128
#define BN 128
#define BK 32
#define STAGES 4
#define KTOT   (K_DIM / BK)      // 128
#define PAD    8
#define LDROW  (BK + PAD)        // 40 halfs = 80 B
#define A_STAGE_BYTES (BM * LDROW * 2)   // 10240
#define B_STAGE_BYTES (BN * LDROW * 2)   // 10240
#define SMEM_BYTES    (STAGES * (A_STAGE_BYTES + B_STAGE_BYTES))   // 81920

// ---------------- Hybrid split ----------------
#define NT_TILES   31                   // tensor n-tiles: cols [0, 3968)
#define FFMA_COL0  (NT_TILES * BN)      // 3968
#define FFMA_COLS  (O_DIM - FFMA_COL0)  // 128
#define GEMM_CTAS  (64 * NT_TILES)      // 1984
// FFMA tile 64x64, 256 threads, 4x4 per thread
#define FBM 64
#define FBN 64
#define FBK 32
#define FROW 40                          // halfs per smem row (80 B: 16B-aligned for cp.async)
#define F_STAGE_BYTES (FBM * FROW * 2)   // 5120
#define FKT (K_DIM / FBK)                // 128
#define FFMA_CTAS ((T_MAX / FBM) * (FFMA_COLS / FBN))   // 128*2 = 256
#define TOTAL_CTAS (GEMM_CTAS + FFMA_CTAS)              // 2240 = 64 groups of 35

// ---------------- Scratch (static device globals; no allocation) ----------------
__device__ __align__(1024) __half g_xq[(size_t)T_MAX * K_DIM];   // 64 MB fp16 (exact e4m3 vals)
__device__ __align__(1024) __half g_wd[(size_t)O_DIM * K_DIM];   // 32 MB fp16 (w * ws)
__device__ float g_xs[T_MAX];

// ---------------- PTX helpers (base ISA only) ----------------
__device__ __forceinline__ uint32_t smem_u32(const void* p) {
    uint32_t a;
    asm("{ .reg .u64 t; cvta.to.shared.u64 t, %1; cvt.u32.u64 %0, t; }" : "=r"(a) : "l"(p));
    return a;
}

#define CP_ASYNC_CG16(saddr, gptr) \
    asm volatile("cp.async.cg.shared.global [%0], [%1], 16;" :: "r"(saddr), "l"(gptr) : "memory")
#define CP_COMMIT() asm volatile("cp.async.commit_group;" ::: "memory")
#define CP_WAIT(n)  asm volatile("cp.async.wait_group %0;" :: "n"(n) : "memory")

#define LDSM_X4(r, addr) \
    asm volatile("ldmatrix.sync.aligned.m8n8.x4.shared.b16 {%0,%1,%2,%3}, [%4];" \
        : "=r"((r)[0]), "=r"((r)[1]), "=r"((r)[2]), "=r"((r)[3]) : "r"(addr))

#define MMA16816(d, a, b0, b1) \
    asm volatile("mma.sync.aligned.m16n8k16.row.col.f32.f16.f16.f32 " \
        "{%0,%1,%2,%3}, {%4,%5,%6,%7}, {%8,%9}, {%0,%1,%2,%3};" \
        : "+f"((d)[0]), "+f"((d)[1]), "+f"((d)[2]), "+f"((d)[3]) \
        : "r"((a)[0]), "r"((a)[1]), "r"((a)[2]), "r"((a)[3]), "r"(b0), "r"(b1))

// ---------------- Kernel 1: per-token amax + e4m3 round-trip -> fp16 ----------------
__device__ __forceinline__ __half2 fp8_roundtrip_h2(float a, float b) {
    float2 f2 = make_float2(a, b);
    __nv_fp8x2_storage_t p = __nv_cvt_float2_to_fp8x2(f2, __NV_SATFINITE, __NV_E4M3);
    __half2_raw hr = __nv_cvt_fp8x2_to_halfraw2(p, __NV_E4M3);
    return *reinterpret_cast<__half2*>(&hr);
}

__global__ void __launch_bounds__(256) quant_x_kernel(
    const float* __restrict__ x, __half* __restrict__ xq, float* __restrict__ xs)
{
    int row = blockIdx.x;
    int tid = threadIdx.x;
    const float4* xr = reinterpret_cast<const float4*>(x + (size_t)row * K_DIM);
    float4 v[4];
    float am = 0.0f;
#pragma unroll
    for (int j = 0; j < 4; j++) {
        v[j] = xr[tid + j * 256];
        am = fmaxf(am, fmaxf(fmaxf(fabsf(v[j].x), fabsf(v[j].y)),
                             fmaxf(fabsf(v[j].z), fabsf(v[j].w))));
    }
#pragma unroll
    for (int o = 16; o > 0; o >>= 1)
        am = fmaxf(am, __shfl_xor_sync(0xffffffffu, am, o));
    __shared__ float red[8];
    if ((tid & 31) == 0) red[tid >> 5] = am;
    __syncthreads();
    float m = red[0];
#pragma unroll
    for (int i = 1; i < 8; i++) m = fmaxf(m, red[i]);
    m = fmaxf(m, 1e-12f);
    float scale = m / FP8_MAX;
    if (tid == 0) xs[row] = scale;
    float rs = 1.0f / scale;
    __half2* outp = reinterpret_cast<__half2*>(xq + (size_t)row * K_DIM);
#pragma unroll
    for (int j = 0; j < 4; j++) {
        int f = tid + j * 256;
        outp[2 * f + 0] = fp8_roundtrip_h2(v[j].x * rs, v[j].y * rs);
        outp[2 * f + 1] = fp8_roundtrip_h2(v[j].z * rs, v[j].w * rs);
    }
}

// ---------------- Kernel 2: blockwise weight dequant -> fp16 ----------------
__global__ void __launch_bounds__(256) dequant_w_kernel(
    const float* __restrict__ w, const float* __restrict__ ws, __half* __restrict__ wd)
{
    size_t idx = ((size_t)blockIdx.x * blockDim.x + threadIdx.x) * 4;
    int o = (int)(idx >> 12);
    int i = (int)(idx & 4095);
    float s = ws[(o >> 7) * (K_DIM / 128) + (i >> 7)];
    float4 v = *reinterpret_cast<const float4*>(w + idx);
    __half2 h0 = __floats2half2_rn(v.x * s, v.y * s);
    __half2 h1 = __floats2half2_rn(v.z * s, v.w * s);
    __half2* p = reinterpret_cast<__half2*>(wd + idx);
    p[0] = h0;
    p[1] = h1;
}

// ---------------- FFMA side: 64x64 tile f32 SIMT GEMM over fp16 operands ----------------
__device__ __forceinline__ void ffma_block(
    char* smem, int fblk,
    float* __restrict__ out, const float* __restrict__ xs,
    const __half* __restrict__ A, const __half* __restrict__ B)
{
    const int tid = threadIdx.x;
    const int tm = tid & 15;
    const int tn = tid >> 4;

    const int fm = fblk >> 1;             // 0..127
    const int fn = fblk & 1;              // 0..1
    const int rowbase = fm * FBM;
    const int colbase = FFMA_COL0 + fn * FBN;

    const __half* gX = A + (size_t)rowbase * K_DIM;
    const __half* gW = B + (size_t)colbase * K_DIM;

    const uint32_t smX = smem_u32(smem);
    const uint32_t smW = smX + STAGES * F_STAGE_BYTES;

    // cp.async coords: 256 chunks (64 rows x 4 x 16B) per operand per stage; 1 each
    const int cr = tid >> 2, cc = tid & 3;

    auto load_f = [&](int s, int kb) {
        uint32_t dX = smX + s * F_STAGE_BYTES + cr * (FROW * 2) + cc * 16;
        uint32_t dW = smW + s * F_STAGE_BYTES + cr * (FROW * 2) + cc * 16;
        const __half* sx = gX + (size_t)cr * K_DIM + kb * FBK + cc * 8;
        const __half* sw = gW + (size_t)cr * K_DIM + kb * FBK + cc * 8;
        CP_ASYNC_CG16(dX, sx);
        CP_ASYNC_CG16(dW, sw);
    };

    float acc[4][4];
#pragma unroll
    for (int i = 0; i < 4; i++)
#pragma unroll
        for (int j = 0; j < 4; j++) acc[i][j] = 0.0f;

#pragma unroll
    for (int s = 0; s < STAGES - 1; s++) {
        load_f(s, s);
        CP_COMMIT();
    }

    for (int kb = 0; kb < FKT; kb++) {
        CP_WAIT(2);
        __syncthreads();

        int nk = kb + (STAGES - 1);
        if (nk < FKT) load_f(nk & (STAGES - 1), nk);
        CP_COMMIT();

        const int st = kb & (STAGES - 1);
        const uint32_t bx = smX + st * F_STAGE_BYTES + tm * (FROW * 2);
        const uint32_t bw = smW + st * F_STAGE_BYTES + tn * (FROW * 2);
#pragma unroll
        for (int kk = 0; kk < FBK / 2; kk++) {
            float2 fx[4], fw[4];
#pragma unroll
            for (int i = 0; i < 4; i++) {
                uint32_t h;
                asm volatile("ld.shared.b32 %0, [%1];" : "=r"(h)
                             : "r"(bx + i * 16 * (FROW * 2) + kk * 4));
                fx[i] = __half22float2(*reinterpret_cast<__half2*>(&h));
            }
#pragma unroll
            for (int j = 0; j < 4; j++) {
                uint32_t h;
                asm volatile("ld.shared.b32 %0, [%1];" : "=r"(h)
                             : "r"(bw + j * 16 * (FROW * 2) + kk * 4));
                fw[j] = __half22float2(*reinterpret_cast<__half2*>(&h));
            }
#pragma unroll
            for (int i = 0; i < 4; i++)
#pragma unroll
                for (int j = 0; j < 4; j++)
                    acc[i][j] = fmaf(fx[i].y, fw[j].y, fmaf(fx[i].x, fw[j].x, acc[i][j]));
        }
    }

    // epilogue: per-row x_scale, scattered f32 stores
#pragma unroll
    for (int i = 0; i < 4; i++) {
        int row = rowbase + tm + 16 * i;
        float s = xs[row];
        float* orow = out + (size_t)row * O_DIM + colbase;
#pragma unroll
        for (int j = 0; j < 4; j++)
            orow[tn + 16 * j] = acc[i][j] * s;
    }
}

// ---------------- Hybrid kernel: tensor CTAs + interleaved FFMA CTAs ----------------
__global__ void __launch_bounds__(256, 2) gemm_hybrid(
    float* __restrict__ out, const float* __restrict__ xs,
    const __half* __restrict__ A, const __half* __restrict__ B)
{
    extern __shared__ char smem[];

    // block-role mapping: 64 groups of 35; in-group idx {7,15,23,31} -> FFMA
    const int bid   = blockIdx.x;
    const int group = bid / 35;
    const int idx   = bid % 35;
    const bool is_f = (idx < 32) && ((idx & 7) == 7);

    if (is_f) {
        int fblk = group * 4 + (idx >> 3);
        ffma_block(smem, fblk, out, xs, A, B);
        return;
    }
    int g = (idx < 32) ? (group * 31 + idx - (idx >> 3)) : (group * 31 + idx - 4);

    const uint32_t smA = smem_u32(smem);
    const uint32_t smB = smA + STAGES * A_STAGE_BYTES;

    const int tid  = threadIdx.x;
    const int lane = tid & 31;
    const int wid  = tid >> 5;
    const int wm   = wid & 1;
    const int wn   = wid >> 1;

    const int ntile = g % NT_TILES;
    const int mtile = g / NT_TILES;

    const __half* gA = A + (size_t)(mtile * BM) * K_DIM;
    const __half* gB = B + (size_t)(ntile * BN) * K_DIM;

    const int lrow = tid >> 2;
    const int lcc  = tid & 3;

    float acc[4][4][4];
#pragma unroll
    for (int a = 0; a < 4; a++)
#pragma unroll
        for (int b = 0; b < 4; b++)
#pragma unroll
            for (int c = 0; c < 4; c++) acc[a][b][c] = 0.0f;

    const uint32_t aBase = smA + (uint32_t)(((wm * 64 + (lane & 15)) * LDROW + (lane >> 4) * 8) * 2);
    const uint32_t bBase = smB + (uint32_t)(((wn * 32 + (lane & 15)) * LDROW + (lane >> 4) * 8) * 2);

    auto load_stage = [&](int s, int kt) {
        const uint32_t sa = smA + s * A_STAGE_BYTES;
        const uint32_t sb = smB + s * B_STAGE_BYTES;
        const __half* ga = gA + kt * BK;
        const __half* gb = gB + kt * BK;
#pragma unroll
        for (int i = 0; i < 2; i++) {
            int row = lrow + i * 64;
            uint32_t so = (uint32_t)(row * (LDROW * 2) + lcc * 16);
            CP_ASYNC_CG16(sa + so, ga + (size_t)row * K_DIM + lcc * 8);
            CP_ASYNC_CG16(sb + so, gb + (size_t)row * K_DIM + lcc * 8);
        }
    };

#pragma unroll
    for (int s = 0; s < STAGES - 1; s++) {
        load_stage(s, s);
        CP_COMMIT();
    }

    for (int kt = 0; kt < KTOT; kt++) {
        CP_WAIT(2);
        __syncthreads();

        int nk = kt + (STAGES - 1);
        if (nk < KTOT) load_stage((nk & (STAGES - 1)), nk);
        CP_COMMIT();

        const int s = kt & (STAGES - 1);
        const uint32_t sa = aBase + s * A_STAGE_BYTES;
        const uint32_t sb = bBase + s * B_STAGE_BYTES;
#pragma unroll
        for (int ks = 0; ks < 2; ks++) {
            const uint32_t ka = sa + ks * 32;
            const uint32_t kb = sb + ks * 32;
            uint32_t af[4][4];
            uint32_t bf[2][4];
#pragma unroll
            for (int mt = 0; mt < 4; mt++) LDSM_X4(af[mt], ka + mt * 16 * (LDROW * 2));
#pragma unroll
            for (int pt = 0; pt < 2; pt++) LDSM_X4(bf[pt], kb + pt * 16 * (LDROW * 2));
#pragma unroll
            for (int mt = 0; mt < 4; mt++) {
#pragma unroll
                for (int nt = 0; nt < 4; nt++) {
                    const int pt = nt >> 1, od = nt & 1;
                    MMA16816(acc[mt][nt], af[mt], bf[pt][od], bf[pt][od + 2]);
                }
            }
        }
    }

    const int rowbase = mtile * BM + wm * 64 + (lane >> 2);
    const int colbase = ntile * BN + wn * 32 + (lane & 3) * 2;
#pragma unroll
    for (int mt = 0; mt < 4; mt++) {
        const int r0 = rowbase + mt * 16;
        const float s0 = xs[r0];
        const float s1 = xs[r0 + 8];
        float* o0 = out + (size_t)r0 * O_DIM + colbase;
        float* o1 = o0 + (size_t)8 * O_DIM;
#pragma unroll
        for (int nt = 0; nt < 4; nt++) {
            float2 v0 = make_float2(acc[mt][nt][0] * s0, acc[mt][nt][1] * s0);
            float2 v1 = make_float2(acc[mt][nt][2] * s1, acc[mt][nt][3] * s1);
            *reinterpret_cast<float2*>(o0 + nt * 8) = v0;
            *reinterpret_cast<float2*>(o1 + nt * 8) = v1;
        }
    }
}

// ---------------- Launch ----------------
extern "C" void kernel_launch(void* const* d_in, const int* in_sizes, int n_in,
                              void* d_out, int out_size)
{
    const float* x  = (const float*)d_in[0];
    const float* w  = (const float*)d_in[1];
    const float* ws = (const float*)d_in[2];
    float* out = (float*)d_out;

    const int K = K_DIM;
    const int T = in_sizes[0] / K;   // 8192
    const int O = in_sizes[1] / K;   // 4096

    void *pxq = nullptr, *pwd = nullptr, *pxs = nullptr;
    cudaGetSymbolAddress(&pxq, g_xq);
    cudaGetSymbolAddress(&pwd, g_wd);
    cudaGetSymbolAddress(&pxs, g_xs);

    quant_x_kernel<<<T, 256>>>(x, (__half*)pxq, (float*)pxs);
    dequant_w_kernel<<<(int)(((size_t)O * K / 4) / 256), 256>>>(w, ws, (__half*)pwd);

    cudaFuncSetAttribute(gemm_hybrid, cudaFuncAttributeMaxDynamicSharedMemorySize, SMEM_BYTES);
    gemm_hybrid<<<TOTAL_CTAS, 256, SMEM_BYTES>>>(out, (float*)pxs,
                                                 (const __half*)pxq, (const __half*)pwd);
}

// round 13
// speedup vs baseline: 1.3292x; 1.3292x over previous
#include <cuda_runtime.h>
#include <cuda_fp16.h>
#include <cuda_fp8.h>
#include <cstdint>

// ---------------- Problem constants (fixed-shape bench) ----------------
#define T_MAX   8192
#define K_DIM   4096
#define O_DIM   4096
#define FP8_MAX 448.0f

// ---------------- GEMM tiling (R3 config, proven 905us) ----------------
#define BM 128
#define BN 128
#define BK 32
#define STAGES 4
#define KTOT   (K_DIM / BK)      // 128
#define PAD    8
#define LDROW  (BK + PAD)        // 40 halfs = 80 B
#define A_STAGE_BYTES (BM * LDROW * 2)   // 10240
#define B_STAGE_BYTES (BN * LDROW * 2)   // 10240
#define SMEM_BYTES    (STAGES * (A_STAGE_BYTES + B_STAGE_BYTES))   // 81920

// Fused prep grid split
#define QUANT_BLOCKS   T_MAX                         // 8192 (one x row each)
#define DEQUANT_BLOCKS ((O_DIM * K_DIM / 4) / 256)   // 16384
#define PREP_BLOCKS    (QUANT_BLOCKS + DEQUANT_BLOCKS)

// ---------------- Scratch (static device globals; no allocation) ----------------
__device__ __align__(1024) __half g_xq[(size_t)T_MAX * K_DIM];   // 64 MB fp16 (exact e4m3 vals)
__device__ __align__(1024) __half g_wd[(size_t)O_DIM * K_DIM];   // 32 MB fp16 (w * ws)
__device__ float g_xs[T_MAX];

// ---------------- PTX helpers (base ISA only) ----------------
__device__ __forceinline__ uint32_t smem_u32(const void* p) {
    uint32_t a;
    asm("{ .reg .u64 t; cvta.to.shared.u64 t, %1; cvt.u32.u64 %0, t; }" : "=r"(a) : "l"(p));
    return a;
}

#define CP_ASYNC_CG16(saddr, gptr) \
    asm volatile("cp.async.cg.shared.global [%0], [%1], 16;" :: "r"(saddr), "l"(gptr) : "memory")
#define CP_COMMIT() asm volatile("cp.async.commit_group;" ::: "memory")
#define CP_WAIT(n)  asm volatile("cp.async.wait_group %0;" :: "n"(n) : "memory")

#define LDSM_X4(r, addr) \
    asm volatile("ldmatrix.sync.aligned.m8n8.x4.shared.b16 {%0,%1,%2,%3}, [%4];" \
        : "=r"((r)[0]), "=r"((r)[1]), "=r"((r)[2]), "=r"((r)[3]) : "r"(addr))

#define MMA16816(d, a, b0, b1) \
    asm volatile("mma.sync.aligned.m16n8k16.row.col.f32.f16.f16.f32 " \
        "{%0,%1,%2,%3}, {%4,%5,%6,%7}, {%8,%9}, {%0,%1,%2,%3};" \
        : "+f"((d)[0]), "+f"((d)[1]), "+f"((d)[2]), "+f"((d)[3]) \
        : "r"((a)[0]), "r"((a)[1]), "r"((a)[2]), "r"((a)[3]), "r"(b0), "r"(b1))

// ---------------- Fused prep: x quant (e4m3 roundtrip -> fp16) + w dequant -> fp16 ----------------
__device__ __forceinline__ __half2 fp8_roundtrip_h2(float a, float b) {
    float2 f2 = make_float2(a, b);
    __nv_fp8x2_storage_t p = __nv_cvt_float2_to_fp8x2(f2, __NV_SATFINITE, __NV_E4M3);
    __half2_raw hr = __nv_cvt_fp8x2_to_halfraw2(p, __NV_E4M3);
    return *reinterpret_cast<__half2*>(&hr);
}

__global__ void __launch_bounds__(256) prep_kernel(
    const float* __restrict__ x,  __half* __restrict__ xq, float* __restrict__ xs,
    const float* __restrict__ w,  const float* __restrict__ ws, __half* __restrict__ wd)
{
    const int tid = threadIdx.x;

    if (blockIdx.x < QUANT_BLOCKS) {
        // ---- per-token amax + e4m3 roundtrip quant of one x row ----
        const int row = blockIdx.x;
        const float4* xr = reinterpret_cast<const float4*>(x + (size_t)row * K_DIM);
        float4 v[4];
        float am = 0.0f;
#pragma unroll
        for (int j = 0; j < 4; j++) {
            v[j] = xr[tid + j * 256];
            am = fmaxf(am, fmaxf(fmaxf(fabsf(v[j].x), fabsf(v[j].y)),
                                 fmaxf(fabsf(v[j].z), fabsf(v[j].w))));
        }
#pragma unroll
        for (int o = 16; o > 0; o >>= 1)
            am = fmaxf(am, __shfl_xor_sync(0xffffffffu, am, o));
        __shared__ float red[8];
        if ((tid & 31) == 0) red[tid >> 5] = am;
        __syncthreads();
        float m = red[0];
#pragma unroll
        for (int i = 1; i < 8; i++) m = fmaxf(m, red[i]);
        m = fmaxf(m, 1e-12f);
        float scale = m / FP8_MAX;
        if (tid == 0) xs[row] = scale;
        float rs = 1.0f / scale;
        __half2* outp = reinterpret_cast<__half2*>(xq + (size_t)row * K_DIM);
#pragma unroll
        for (int j = 0; j < 4; j++) {
            int f = tid + j * 256;
            outp[2 * f + 0] = fp8_roundtrip_h2(v[j].x * rs, v[j].y * rs);
            outp[2 * f + 1] = fp8_roundtrip_h2(v[j].z * rs, v[j].w * rs);
        }
    } else {
        // ---- blockwise weight dequant ----
        size_t idx = ((size_t)(blockIdx.x - QUANT_BLOCKS) * 256 + tid) * 4;
        int o = (int)(idx >> 12);
        int i = (int)(idx & 4095);
        float s = ws[(o >> 7) * (K_DIM / 128) + (i >> 7)];
        float4 v = *reinterpret_cast<const float4*>(w + idx);
        __half2 h0 = __floats2half2_rn(v.x * s, v.y * s);
        __half2 h1 = __floats2half2_rn(v.z * s, v.w * s);
        __half2* p = reinterpret_cast<__half2*>(wd + idx);
        p[0] = h0;
        p[1] = h1;
    }
}

// ---------------- GEMM (R3, proven): f16 mma.sync 128x128x32, 4-stage cp.async ----------------
__global__ void __launch_bounds__(256, 2) gemm_kernel(
    float* __restrict__ out, const float* __restrict__ xs,
    const __half* __restrict__ A, const __half* __restrict__ B, int ntiles_n)
{
    extern __shared__ char smem[];
    const uint32_t smA = smem_u32(smem);
    const uint32_t smB = smA + STAGES * A_STAGE_BYTES;

    const int tid  = threadIdx.x;
    const int lane = tid & 31;
    const int wid  = tid >> 5;
    const int wm   = wid & 1;
    const int wn   = wid >> 1;

    const int ntile = blockIdx.x % ntiles_n;
    const int mtile = blockIdx.x / ntiles_n;

    const __half* gA = A + (size_t)(mtile * BM) * K_DIM;
    const __half* gB = B + (size_t)(ntile * BN) * K_DIM;

    const int lrow = tid >> 2;
    const int lcc  = tid & 3;

    float acc[4][4][4];
#pragma unroll
    for (int a = 0; a < 4; a++)
#pragma unroll
        for (int b = 0; b < 4; b++)
#pragma unroll
            for (int c = 0; c < 4; c++) acc[a][b][c] = 0.0f;

    const uint32_t aBase = smA + (uint32_t)(((wm * 64 + (lane & 15)) * LDROW + (lane >> 4) * 8) * 2);
    const uint32_t bBase = smB + (uint32_t)(((wn * 32 + (lane & 15)) * LDROW + (lane >> 4) * 8) * 2);

    auto load_stage = [&](int s, int kt) {
        const uint32_t sa = smA + s * A_STAGE_BYTES;
        const uint32_t sb = smB + s * B_STAGE_BYTES;
        const __half* ga = gA + kt * BK;
        const __half* gb = gB + kt * BK;
#pragma unroll
        for (int i = 0; i < 2; i++) {
            int row = lrow + i * 64;
            uint32_t so = (uint32_t)(row * (LDROW * 2) + lcc * 16);
            CP_ASYNC_CG16(sa + so, ga + (size_t)row * K_DIM + lcc * 8);
            CP_ASYNC_CG16(sb + so, gb + (size_t)row * K_DIM + lcc * 8);
        }
    };

#pragma unroll
    for (int s = 0; s < STAGES - 1; s++) {
        load_stage(s, s);
        CP_COMMIT();
    }

    for (int kt = 0; kt < KTOT; kt++) {
        CP_WAIT(2);
        __syncthreads();

        int nk = kt + (STAGES - 1);
        if (nk < KTOT) load_stage((nk & (STAGES - 1)), nk);
        CP_COMMIT();

        const int s = kt & (STAGES - 1);
        const uint32_t sa = aBase + s * A_STAGE_BYTES;
        const uint32_t sb = bBase + s * B_STAGE_BYTES;
#pragma unroll
        for (int ks = 0; ks < 2; ks++) {
            const uint32_t ka = sa + ks * 32;
            const uint32_t kb = sb + ks * 32;
            uint32_t af[4][4];
            uint32_t bf[2][4];
#pragma unroll
            for (int mt = 0; mt < 4; mt++) LDSM_X4(af[mt], ka + mt * 16 * (LDROW * 2));
#pragma unroll
            for (int pt = 0; pt < 2; pt++) LDSM_X4(bf[pt], kb + pt * 16 * (LDROW * 2));
#pragma unroll
            for (int mt = 0; mt < 4; mt++) {
#pragma unroll
                for (int nt = 0; nt < 4; nt++) {
                    const int pt = nt >> 1, od = nt & 1;
                    MMA16816(acc[mt][nt], af[mt], bf[pt][od], bf[pt][od + 2]);
                }
            }
        }
    }

    const int rowbase = mtile * BM + wm * 64 + (lane >> 2);
    const int colbase = ntile * BN + wn * 32 + (lane & 3) * 2;
#pragma unroll
    for (int mt = 0; mt < 4; mt++) {
        const int r0 = rowbase + mt * 16;
        const float s0 = xs[r0];
        const float s1 = xs[r0 + 8];
        float* o0 = out + (size_t)r0 * O_DIM + colbase;
        float* o1 = o0 + (size_t)8 * O_DIM;
#pragma unroll
        for (int nt = 0; nt < 4; nt++) {
            float2 v0 = make_float2(acc[mt][nt][0] * s0, acc[mt][nt][1] * s0);
            float2 v1 = make_float2(acc[mt][nt][2] * s1, acc[mt][nt][3] * s1);
            *reinterpret_cast<float2*>(o0 + nt * 8) = v0;
            *reinterpret_cast<float2*>(o1 + nt * 8) = v1;
        }
    }
}

// ---------------- Launch ----------------
extern "C" void kernel_launch(void* const* d_in, const int* in_sizes, int n_in,
                              void* d_out, int out_size)
{
    const float* x  = (const float*)d_in[0];
    const float* w  = (const float*)d_in[1];
    const float* ws = (const float*)d_in[2];
    float* out = (float*)d_out;

    const int K = K_DIM;
    const int T = in_sizes[0] / K;   // 8192
    const int O = in_sizes[1] / K;   // 4096

    void *pxq = nullptr, *pwd = nullptr, *pxs = nullptr;
    cudaGetSymbolAddress(&pxq, g_xq);
    cudaGetSymbolAddress(&pwd, g_wd);
    cudaGetSymbolAddress(&pxs, g_xs);

    prep_kernel<<<PREP_BLOCKS, 256>>>(x, (__half*)pxq, (float*)pxs,
                                      w, ws, (__half*)pwd);

    cudaFuncSetAttribute(gemm_kernel, cudaFuncAttributeMaxDynamicSharedMemorySize, SMEM_BYTES);
    const int ntiles_n = O / BN;                 // 32
    const int grid = (T / BM) * ntiles_n;        // 2048
    gemm_kernel<<<grid, 256, SMEM_BYTES>>>(out, (float*)pxs,
                                           (const __half*)pxq, (const __half*)pwd, ntiles_n);
}

// round 14
// speedup vs baseline: 1.3391x; 1.0074x over previous
#include <cuda_runtime.h>
#include <cuda_fp16.h>
#include <cuda_fp8.h>
#include <cstdint>

// ---------------- Problem constants (fixed-shape bench) ----------------
#define T_MAX   8192
#define K_DIM   4096
#define O_DIM   4096
#define FP8_MAX 448.0f

// ---------------- GEMM tiling ----------------
#define BM 128
#define BN 128
#define BK 32
#define STAGES 4
#define KTOT   (K_DIM / BK)      // 128
#define PAD    8
#define LDROW  (BK + PAD)        // 40 halfs = 80 B
#define ROWB   (LDROW * 2)       // 80
#define A_STAGE_BYTES (BM * ROWB)        // 10240
#define B_STAGE_BYTES (BN * ROWB)        // 10240
#define SMEM_BYTES    (STAGES * (A_STAGE_BYTES + B_STAGE_BYTES))   // 81920

// Fused prep grid split
#define QUANT_BLOCKS   T_MAX                         // 8192 (one x row each)
#define DEQUANT_BLOCKS ((O_DIM * K_DIM / 4) / 256)   // 16384
#define PREP_BLOCKS    (QUANT_BLOCKS + DEQUANT_BLOCKS)

// ---------------- Scratch (static device globals; no allocation) ----------------
__device__ __align__(1024) __half g_xq[(size_t)T_MAX * K_DIM];   // 64 MB fp16 (exact e4m3 vals)
__device__ __align__(1024) __half g_wd[(size_t)O_DIM * K_DIM];   // 32 MB fp16 (w * ws)
__device__ float g_xs[T_MAX];

// ---------------- PTX helpers (base ISA only) ----------------
__device__ __forceinline__ uint32_t smem_u32(const void* p) {
    uint32_t a;
    asm("{ .reg .u64 t; cvta.to.shared.u64 t, %1; cvt.u32.u64 %0, t; }" : "=r"(a) : "l"(p));
    return a;
}

#define CP_ASYNC_CG16(saddr, gptr) \
    asm volatile("cp.async.cg.shared.global [%0], [%1], 16;" :: "r"(saddr), "l"(gptr) : "memory")
#define CP_COMMIT() asm volatile("cp.async.commit_group;" ::: "memory")
#define CP_WAIT(n)  asm volatile("cp.async.wait_group %0;" :: "n"(n) : "memory")

#define LDSM_X4(r, addr) \
    asm volatile("ldmatrix.sync.aligned.m8n8.x4.shared.b16 {%0,%1,%2,%3}, [%4];" \
        : "=r"((r)[0]), "=r"((r)[1]), "=r"((r)[2]), "=r"((r)[3]) : "r"(addr))

#define MMA16816(d, a, b0, b1) \
    asm volatile("mma.sync.aligned.m16n8k16.row.col.f32.f16.f16.f32 " \
        "{%0,%1,%2,%3}, {%4,%5,%6,%7}, {%8,%9}, {%0,%1,%2,%3};" \
        : "+f"((d)[0]), "+f"((d)[1]), "+f"((d)[2]), "+f"((d)[3]) \
        : "r"((a)[0]), "r"((a)[1]), "r"((a)[2]), "r"((a)[3]), "r"(b0), "r"(b1))

// ---------------- Fused prep: x quant (e4m3 roundtrip -> fp16) + w dequant -> fp16 ----------------
__device__ __forceinline__ __half2 fp8_roundtrip_h2(float a, float b) {
    float2 f2 = make_float2(a, b);
    __nv_fp8x2_storage_t p = __nv_cvt_float2_to_fp8x2(f2, __NV_SATFINITE, __NV_E4M3);
    __half2_raw hr = __nv_cvt_fp8x2_to_halfraw2(p, __NV_E4M3);
    return *reinterpret_cast<__half2*>(&hr);
}

__global__ void __launch_bounds__(256) prep_kernel(
    const float* __restrict__ x,  __half* __restrict__ xq, float* __restrict__ xs,
    const float* __restrict__ w,  const float* __restrict__ ws, __half* __restrict__ wd)
{
    const int tid = threadIdx.x;

    if (blockIdx.x < QUANT_BLOCKS) {
        const int row = blockIdx.x;
        const float4* xr = reinterpret_cast<const float4*>(x + (size_t)row * K_DIM);
        float4 v[4];
        float am = 0.0f;
#pragma unroll
        for (int j = 0; j < 4; j++) {
            v[j] = xr[tid + j * 256];
            am = fmaxf(am, fmaxf(fmaxf(fabsf(v[j].x), fabsf(v[j].y)),
                                 fmaxf(fabsf(v[j].z), fabsf(v[j].w))));
        }
#pragma unroll
        for (int o = 16; o > 0; o >>= 1)
            am = fmaxf(am, __shfl_xor_sync(0xffffffffu, am, o));
        __shared__ float red[8];
        if ((tid & 31) == 0) red[tid >> 5] = am;
        __syncthreads();
        float m = red[0];
#pragma unroll
        for (int i = 1; i < 8; i++) m = fmaxf(m, red[i]);
        m = fmaxf(m, 1e-12f);
        float scale = m / FP8_MAX;
        if (tid == 0) xs[row] = scale;
        float rs = 1.0f / scale;
        __half2* outp = reinterpret_cast<__half2*>(xq + (size_t)row * K_DIM);
#pragma unroll
        for (int j = 0; j < 4; j++) {
            int f = tid + j * 256;
            outp[2 * f + 0] = fp8_roundtrip_h2(v[j].x * rs, v[j].y * rs);
            outp[2 * f + 1] = fp8_roundtrip_h2(v[j].z * rs, v[j].w * rs);
        }
    } else {
        size_t idx = ((size_t)(blockIdx.x - QUANT_BLOCKS) * 256 + tid) * 4;
        int o = (int)(idx >> 12);
        int i = (int)(idx & 4095);
        float s = ws[(o >> 7) * (K_DIM / 128) + (i >> 7)];
        float4 v = *reinterpret_cast<const float4*>(w + idx);
        __half2 h0 = __floats2half2_rn(v.x * s, v.y * s);
        __half2 h1 = __floats2half2_rn(v.z * s, v.w * s);
        __half2* p = reinterpret_cast<__half2*>(wd + idx);
        p[0] = h0;
        p[1] = h1;
    }
}

// ---------------- GEMM: f16 mma.sync 128x128x32, 4-stage cp.async,
//                  register fragment double-buffering (sm80-style) ----------------
__global__ void __launch_bounds__(256, 1) gemm_kernel(
    float* __restrict__ out, const float* __restrict__ xs,
    const __half* __restrict__ A, const __half* __restrict__ B, int ntiles_n)
{
    extern __shared__ char smem[];
    const uint32_t smA = smem_u32(smem);
    const uint32_t smB = smA + STAGES * A_STAGE_BYTES;

    const int tid  = threadIdx.x;
    const int lane = tid & 31;
    const int wid  = tid >> 5;
    const int wm   = wid & 1;
    const int wn   = wid >> 1;

    const int ntile = blockIdx.x % ntiles_n;
    const int mtile = blockIdx.x / ntiles_n;

    const __half* gA = A + (size_t)(mtile * BM) * K_DIM;
    const __half* gB = B + (size_t)(ntile * BN) * K_DIM;

    const int lrow = tid >> 2;
    const int lcc  = tid & 3;

    float acc[4][4][4];
#pragma unroll
    for (int a = 0; a < 4; a++)
#pragma unroll
        for (int b = 0; b < 4; b++)
#pragma unroll
            for (int c = 0; c < 4; c++) acc[a][b][c] = 0.0f;

    const uint32_t aBase = smA + (uint32_t)((wm * 64 + (lane & 15)) * ROWB + (lane >> 4) * 16);
    const uint32_t bBase = smB + (uint32_t)((wn * 32 + (lane & 15)) * ROWB + (lane >> 4) * 16);

    auto load_stage = [&](int s, int kt) {
        const uint32_t sa = smA + s * A_STAGE_BYTES;
        const uint32_t sb = smB + s * B_STAGE_BYTES;
        const __half* ga = gA + kt * BK;
        const __half* gb = gB + kt * BK;
#pragma unroll
        for (int i = 0; i < 2; i++) {
            int row = lrow + i * 64;
            uint32_t so = (uint32_t)(row * ROWB + lcc * 16);
            CP_ASYNC_CG16(sa + so, ga + (size_t)row * K_DIM + lcc * 8);
            CP_ASYNC_CG16(sb + so, gb + (size_t)row * K_DIM + lcc * 8);
        }
    };

    // two register fragment sets
    uint32_t afX[4][4], bfX[2][4];   // even k-step (preloaded)
    uint32_t afY[4][4], bfY[2][4];   // odd k-step

    // prologue: 3 stages in flight, then preload fragments for (kt=0, ks=0)
#pragma unroll
    for (int s = 0; s < STAGES - 1; s++) {
        load_stage(s, s);
        CP_COMMIT();
    }
    CP_WAIT(2);
    __syncthreads();
#pragma unroll
    for (int mt = 0; mt < 4; mt++) LDSM_X4(afX[mt], aBase + mt * 16 * ROWB);
#pragma unroll
    for (int pt = 0; pt < 2; pt++) LDSM_X4(bfX[pt], bBase + pt * 16 * ROWB);

    for (int kt = 0; kt < KTOT; kt++) {
        const int s = kt & (STAGES - 1);
        const uint32_t sa = aBase + s * A_STAGE_BYTES;
        const uint32_t sb = bBase + s * B_STAGE_BYTES;

        // issue LDSM for (kt, ks=1) — overlaps with MMAs on X below
#pragma unroll
        for (int mt = 0; mt < 4; mt++) LDSM_X4(afY[mt], sa + 32 + mt * 16 * ROWB);
#pragma unroll
        for (int pt = 0; pt < 2; pt++) LDSM_X4(bfY[pt], sb + 32 + pt * 16 * ROWB);

        // MMAs for (kt, ks=0)
#pragma unroll
        for (int mt = 0; mt < 4; mt++) {
#pragma unroll
            for (int nt = 0; nt < 4; nt++) {
                const int pt = nt >> 1, od = nt & 1;
                MMA16816(acc[mt][nt], afX[mt], bfX[pt][od], bfX[pt][od + 2]);
            }
        }

        // prefetch next smem stage
        int nk = kt + (STAGES - 1);
        if (nk < KTOT) load_stage(nk & (STAGES - 1), nk);
        CP_COMMIT();

        // advance to next stage and preload (kt+1, ks=0) fragments,
        // overlapping with MMAs on Y below
        if (kt + 1 < KTOT) {
            CP_WAIT(2);
            __syncthreads();
            const int s2 = (kt + 1) & (STAGES - 1);
            const uint32_t sa2 = aBase + s2 * A_STAGE_BYTES;
            const uint32_t sb2 = bBase + s2 * B_STAGE_BYTES;
#pragma unroll
            for (int mt = 0; mt < 4; mt++) LDSM_X4(afX[mt], sa2 + mt * 16 * ROWB);
#pragma unroll
            for (int pt = 0; pt < 2; pt++) LDSM_X4(bfX[pt], sb2 + pt * 16 * ROWB);
        }

        // MMAs for (kt, ks=1)
#pragma unroll
        for (int mt = 0; mt < 4; mt++) {
#pragma unroll
            for (int nt = 0; nt < 4; nt++) {
                const int pt = nt >> 1, od = nt & 1;
                MMA16816(acc[mt][nt], afY[mt], bfY[pt][od], bfY[pt][od + 2]);
            }
        }
    }

    // epilogue: scale by per-token x_scale, store f32
    const int rowbase = mtile * BM + wm * 64 + (lane >> 2);
    const int colbase = ntile * BN + wn * 32 + (lane & 3) * 2;
#pragma unroll
    for (int mt = 0; mt < 4; mt++) {
        const int r0 = rowbase + mt * 16;
        const float s0 = xs[r0];
        const float s1 = xs[r0 + 8];
        float* o0 = out + (size_t)r0 * O_DIM + colbase;
        float* o1 = o0 + (size_t)8 * O_DIM;
#pragma unroll
        for (int nt = 0; nt < 4; nt++) {
            float2 v0 = make_float2(acc[mt][nt][0] * s0, acc[mt][nt][1] * s0);
            float2 v1 = make_float2(acc[mt][nt][2] * s1, acc[mt][nt][3] * s1);
            *reinterpret_cast<float2*>(o0 + nt * 8) = v0;
            *reinterpret_cast<float2*>(o1 + nt * 8) = v1;
        }
    }
}

// ---------------- Launch ----------------
extern "C" void kernel_launch(void* const* d_in, const int* in_sizes, int n_in,
                              void* d_out, int out_size)
{
    const float* x  = (const float*)d_in[0];
    const float* w  = (const float*)d_in[1];
    const float* ws = (const float*)d_in[2];
    float* out = (float*)d_out;

    const int K = K_DIM;
    const int T = in_sizes[0] / K;   // 8192
    const int O = in_sizes[1] / K;   // 4096

    void *pxq = nullptr, *pwd = nullptr, *pxs = nullptr;
    cudaGetSymbolAddress(&pxq, g_xq);
    cudaGetSymbolAddress(&pwd, g_wd);
    cudaGetSymbolAddress(&pxs, g_xs);

    prep_kernel<<<PREP_BLOCKS, 256>>>(x, (__half*)pxq, (float*)pxs,
                                      w, ws, (__half*)pwd);

    cudaFuncSetAttribute(gemm_kernel, cudaFuncAttributeMaxDynamicSharedMemorySize, SMEM_BYTES);
    const int ntiles_n = O / BN;                 // 32
    const int grid = (T / BM) * ntiles_n;        // 2048
    gemm_kernel<<<grid, 256, SMEM_BYTES>>>(out, (float*)pxs,
                                           (const __half*)pxq, (const __half*)pwd, ntiles_n);
}

// round 17
// speedup vs baseline: 1.3544x; 1.0115x over previous
#include <cuda_runtime.h>
#include <cuda_fp16.h>
#include <cuda_fp8.h>
#include <cstdint>

// ---------------- Problem constants (fixed-shape bench) ----------------
#define T_MAX   8192
#define K_DIM   4096
#define O_DIM   4096
#define FP8_MAX 448.0f

// ---------------- GEMM tiling (R14 config, proven 848us GEMM) ----------------
#define BM 128
#define BN 128
#define BK 32
#define STAGES 4
#define KTOT   (K_DIM / BK)      // 128
#define PAD    8
#define LDROW  (BK + PAD)        // 40 halfs = 80 B
#define ROWB   (LDROW * 2)       // 80
#define A_STAGE_BYTES (BM * ROWB)        // 10240
#define B_STAGE_BYTES (BN * ROWB)        // 10240
#define SMEM_BYTES    (STAGES * (A_STAGE_BYTES + B_STAGE_BYTES))   // 81920

// Overlap split: prepA covers x rows [0, PRE_ROWS) (mtiles 0..PRE_MT-1);
// side stream covers rows [PRE_ROWS, 8192) and bumps per-mtile counters.
#define PRE_MT    6
#define PRE_ROWS  (PRE_MT * BM)          // 768
#define SIDE_ROWS (T_MAX - PRE_ROWS)     // 7424
#define W_BLOCKS  ((O_DIM * K_DIM / 4) / 256)   // 16384
#define PREPA_BLOCKS (W_BLOCKS + PRE_ROWS)

// ---------------- Scratch (static device globals; no allocation) ----------------
__device__ __align__(1024) __half g_xq[(size_t)T_MAX * K_DIM];   // 64 MB fp16 (exact e4m3 vals)
__device__ __align__(1024) __half g_wd[(size_t)O_DIM * K_DIM];   // 32 MB fp16 (w * ws)
__device__ float g_xs[T_MAX];
__device__ int   g_xcnt[T_MAX / BM];     // per-mtile completed-row counters (reset each call)

// ---------------- PTX helpers (base ISA only) ----------------
__device__ __forceinline__ uint32_t smem_u32(const void* p) {
    uint32_t a;
    asm("{ .reg .u64 t; cvta.to.shared.u64 t, %1; cvt.u32.u64 %0, t; }" : "=r"(a) : "l"(p));
    return a;
}

#define CP_ASYNC_CG16(saddr, gptr) \
    asm volatile("cp.async.cg.shared.global [%0], [%1], 16;" :: "r"(saddr), "l"(gptr) : "memory")
#define CP_COMMIT() asm volatile("cp.async.commit_group;" ::: "memory")
#define CP_WAIT(n)  asm volatile("cp.async.wait_group %0;" :: "n"(n) : "memory")

#define LDSM_X4(r, addr) \
    asm volatile("ldmatrix.sync.aligned.m8n8.x4.shared.b16 {%0,%1,%2,%3}, [%4];" \
        : "=r"((r)[0]), "=r"((r)[1]), "=r"((r)[2]), "=r"((r)[3]) : "r"(addr))

#define MMA16816(d, a, b0, b1) \
    asm volatile("mma.sync.aligned.m16n8k16.row.col.f32.f16.f16.f32 " \
        "{%0,%1,%2,%3}, {%4,%5,%6,%7}, {%8,%9}, {%0,%1,%2,%3};" \
        : "+f"((d)[0]), "+f"((d)[1]), "+f"((d)[2]), "+f"((d)[3]) \
        : "r"((a)[0]), "r"((a)[1]), "r"((a)[2]), "r"((a)[3]), "r"(b0), "r"(b1))

// ---------------- Quant helpers ----------------
__device__ __forceinline__ __half2 fp8_roundtrip_h2(float a, float b) {
    float2 f2 = make_float2(a, b);
    __nv_fp8x2_storage_t p = __nv_cvt_float2_to_fp8x2(f2, __NV_SATFINITE, __NV_E4M3);
    __half2_raw hr = __nv_cvt_fp8x2_to_halfraw2(p, __NV_E4M3);
    return *reinterpret_cast<__half2*>(&hr);
}

// One x row, 256 threads cooperating. Idempotent (same inputs -> same bytes).
__device__ __forceinline__ void quant_row(const float* __restrict__ x,
                                          __half* __restrict__ xq,
                                          float* __restrict__ xs, int row, int tid,
                                          float* red)
{
    const float4* xr = reinterpret_cast<const float4*>(x + (size_t)row * K_DIM);
    float4 v[4];
    float am = 0.0f;
#pragma unroll
    for (int j = 0; j < 4; j++) {
        v[j] = xr[tid + j * 256];
        am = fmaxf(am, fmaxf(fmaxf(fabsf(v[j].x), fabsf(v[j].y)),
                             fmaxf(fabsf(v[j].z), fabsf(v[j].w))));
    }
#pragma unroll
    for (int o = 16; o > 0; o >>= 1)
        am = fmaxf(am, __shfl_xor_sync(0xffffffffu, am, o));
    if ((tid & 31) == 0) red[tid >> 5] = am;
    __syncthreads();
    float m = red[0];
#pragma unroll
    for (int i = 1; i < 8; i++) m = fmaxf(m, red[i]);
    __syncthreads();
    m = fmaxf(m, 1e-12f);
    float scale = m / FP8_MAX;
    if (tid == 0) xs[row] = scale;
    float rs = 1.0f / scale;
    __half2* outp = reinterpret_cast<__half2*>(xq + (size_t)row * K_DIM);
#pragma unroll
    for (int j = 0; j < 4; j++) {
        int f = tid + j * 256;
        outp[2 * f + 0] = fp8_roundtrip_h2(v[j].x * rs, v[j].y * rs);
        outp[2 * f + 1] = fp8_roundtrip_h2(v[j].z * rs, v[j].w * rs);
    }
}

// ---------------- Reset: zero per-mtile counters (runs first, every call) ----------------
__global__ void reset_kernel() {
    if (threadIdx.x < T_MAX / BM) g_xcnt[threadIdx.x] = 0;
}

// ---------------- Prep A (main stream): w dequant (all) + x rows [0, PRE_ROWS) ----------------
__global__ void __launch_bounds__(256) prep_wxA_kernel(
    const float* __restrict__ x,  __half* __restrict__ xq, float* __restrict__ xs,
    const float* __restrict__ w,  const float* __restrict__ ws, __half* __restrict__ wd)
{
    const int tid = threadIdx.x;
    if (blockIdx.x < W_BLOCKS) {
        size_t idx = ((size_t)blockIdx.x * 256 + tid) * 4;
        int o = (int)(idx >> 12);
        int i = (int)(idx & 4095);
        float s = ws[(o >> 7) * (K_DIM / 128) + (i >> 7)];
        float4 v = *reinterpret_cast<const float4*>(w + idx);
        __half2 h0 = __floats2half2_rn(v.x * s, v.y * s);
        __half2 h1 = __floats2half2_rn(v.z * s, v.w * s);
        __half2* p = reinterpret_cast<__half2*>(wd + idx);
        p[0] = h0;
        p[1] = h1;
    } else {
        __shared__ float red[8];
        quant_row(x, xq, xs, (int)(blockIdx.x - W_BLOCKS), tid, red);
    }
}

// ---------------- Side stream: x rows [PRE_ROWS, T_MAX), sets per-mtile counters ----------------
__global__ void __launch_bounds__(256) quant_x_side_kernel(
    const float* __restrict__ x, __half* __restrict__ xq, float* __restrict__ xs)
{
    __shared__ float red[8];
    const int row = PRE_ROWS + blockIdx.x;
    quant_row(x, xq, xs, row, threadIdx.x, red);
    __threadfence();
    __syncthreads();
    if (threadIdx.x == 0) atomicAdd(&g_xcnt[row >> 7], 1);
}

// ---------------- GEMM (R14, proven) + flag gate for mtile >= PRE_MT ----------------
__global__ void __launch_bounds__(256, 1) gemm_kernel(
    float* __restrict__ out, const float* __restrict__ xs_,
    const __half* __restrict__ A, const __half* __restrict__ B,
    const float* __restrict__ x)
{
    extern __shared__ char smem[];
    const uint32_t smA = smem_u32(smem);
    const uint32_t smB = smA + STAGES * A_STAGE_BYTES;

    const int tid  = threadIdx.x;
    const int lane = tid & 31;
    const int wid  = tid >> 5;
    const int wm   = wid & 1;
    const int wn   = wid >> 1;

    const int ntile = blockIdx.x & 31;
    const int mtile = blockIdx.x >> 5;

    // Gate: wait until this mtile's x rows are quantized (side stream).
    if (mtile >= PRE_MT) {
        volatile int* cnt = &g_xcnt[mtile];
        bool ready = (*cnt >= BM);
        if (!ready) {
            int spins = 0;
            while (*cnt < BM && spins < 120000) { __nanosleep(64); spins++; }
            if (*cnt < BM) {
                // Fallback (pathological scheduling only): quantize our rows
                // ourselves. Idempotent — identical bytes to the side kernel.
                __shared__ float redf[8];
                for (int r = 0; r < BM; r++) {
                    __syncthreads();
                    quant_row(x, (__half*)A, (float*)xs_, mtile * BM + r, tid, redf);
                }
                __threadfence();
            }
        }
        __threadfence();
        __syncthreads();
    }

    const __half* gA = A + (size_t)(mtile * BM) * K_DIM;
    const __half* gB = B + (size_t)(ntile * BN) * K_DIM;

    const int lrow = tid >> 2;
    const int lcc  = tid & 3;

    float acc[4][4][4];
#pragma unroll
    for (int a = 0; a < 4; a++)
#pragma unroll
        for (int b = 0; b < 4; b++)
#pragma unroll
            for (int c = 0; c < 4; c++) acc[a][b][c] = 0.0f;

    const uint32_t aBase = smA + (uint32_t)((wm * 64 + (lane & 15)) * ROWB + (lane >> 4) * 16);
    const uint32_t bBase = smB + (uint32_t)((wn * 32 + (lane & 15)) * ROWB + (lane >> 4) * 16);

    auto load_stage = [&](int s, int kt) {
        const uint32_t sa = smA + s * A_STAGE_BYTES;
        const uint32_t sb = smB + s * B_STAGE_BYTES;
        const __half* ga = gA + kt * BK;
        const __half* gb = gB + kt * BK;
#pragma unroll
        for (int i = 0; i < 2; i++) {
            int row = lrow + i * 64;
            uint32_t so = (uint32_t)(row * ROWB + lcc * 16);
            CP_ASYNC_CG16(sa + so, ga + (size_t)row * K_DIM + lcc * 8);
            CP_ASYNC_CG16(sb + so, gb + (size_t)row * K_DIM + lcc * 8);
        }
    };

    uint32_t afX[4][4], bfX[2][4];
    uint32_t afY[4][4], bfY[2][4];

#pragma unroll
    for (int s = 0; s < STAGES - 1; s++) {
        load_stage(s, s);
        CP_COMMIT();
    }
    CP_WAIT(2);
    __syncthreads();
#pragma unroll
    for (int mt = 0; mt < 4; mt++) LDSM_X4(afX[mt], aBase + mt * 16 * ROWB);
#pragma unroll
    for (int pt = 0; pt < 2; pt++) LDSM_X4(bfX[pt], bBase + pt * 16 * ROWB);

    for (int kt = 0; kt < KTOT; kt++) {
        const int s = kt & (STAGES - 1);
        const uint32_t sa = aBase + s * A_STAGE_BYTES;
        const uint32_t sb = bBase + s * B_STAGE_BYTES;

#pragma unroll
        for (int mt = 0; mt < 4; mt++) LDSM_X4(afY[mt], sa + 32 + mt * 16 * ROWB);
#pragma unroll
        for (int pt = 0; pt < 2; pt++) LDSM_X4(bfY[pt], sb + 32 + pt * 16 * ROWB);

#pragma unroll
        for (int mt = 0; mt < 4; mt++) {
#pragma unroll
            for (int nt = 0; nt < 4; nt++) {
                const int pt = nt >> 1, od = nt & 1;
                MMA16816(acc[mt][nt], afX[mt], bfX[pt][od], bfX[pt][od + 2]);
            }
        }

        int nk = kt + (STAGES - 1);
        if (nk < KTOT) load_stage(nk & (STAGES - 1), nk);
        CP_COMMIT();

        if (kt + 1 < KTOT) {
            CP_WAIT(2);
            __syncthreads();
            const int s2 = (kt + 1) & (STAGES - 1);
            const uint32_t sa2 = aBase + s2 * A_STAGE_BYTES;
            const uint32_t sb2 = bBase + s2 * B_STAGE_BYTES;
#pragma unroll
            for (int mt = 0; mt < 4; mt++) LDSM_X4(afX[mt], sa2 + mt * 16 * ROWB);
#pragma unroll
            for (int pt = 0; pt < 2; pt++) LDSM_X4(bfX[pt], sb2 + pt * 16 * ROWB);
        }

#pragma unroll
        for (int mt = 0; mt < 4; mt++) {
#pragma unroll
            for (int nt = 0; nt < 4; nt++) {
                const int pt = nt >> 1, od = nt & 1;
                MMA16816(acc[mt][nt], afY[mt], bfY[pt][od], bfY[pt][od + 2]);
            }
        }
    }

    const int rowbase = mtile * BM + wm * 64 + (lane >> 2);
    const int colbase = ntile * BN + wn * 32 + (lane & 3) * 2;
#pragma unroll
    for (int mt = 0; mt < 4; mt++) {
        const int r0 = rowbase + mt * 16;
        const float s0 = xs_[r0];
        const float s1 = xs_[r0 + 8];
        float* o0 = out + (size_t)r0 * O_DIM + colbase;
        float* o1 = o0 + (size_t)8 * O_DIM;
#pragma unroll
        for (int nt = 0; nt < 4; nt++) {
            float2 v0 = make_float2(acc[mt][nt][0] * s0, acc[mt][nt][1] * s0);
            float2 v1 = make_float2(acc[mt][nt][2] * s1, acc[mt][nt][3] * s1);
            *reinterpret_cast<float2*>(o0 + nt * 8) = v0;
            *reinterpret_cast<float2*>(o1 + nt * 8) = v1;
        }
    }
}

// ---------------- Launch: fork to cudaStreamPerThread (no stream creation) ----------------
extern "C" void kernel_launch(void* const* d_in, const int* in_sizes, int n_in,
                              void* d_out, int out_size)
{
    const float* x  = (const float*)d_in[0];
    const float* w  = (const float*)d_in[1];
    const float* ws = (const float*)d_in[2];
    float* out = (float*)d_out;

    void *pxq = nullptr, *pwd = nullptr, *pxs = nullptr;
    cudaGetSymbolAddress(&pxq, g_xq);
    cudaGetSymbolAddress(&pwd, g_wd);
    cudaGetSymbolAddress(&pxs, g_xs);

    cudaFuncSetAttribute(gemm_kernel, cudaFuncAttributeMaxDynamicSharedMemorySize, SMEM_BYTES);

    // Events only (no stream creation — side stream is cudaStreamPerThread).
    // Host-side objects; leaked intentionally (host runs kernel_launch a few
    // times; destroying mid-capture is illegal). DisableTiming => no device mem.
    cudaEvent_t eR, eJ;
    cudaEventCreateWithFlags(&eR, cudaEventDisableTiming);
    cudaEventCreateWithFlags(&eJ, cudaEventDisableTiming);

    // main: reset counters, then prepA (w + x rows [0, PRE_ROWS))
    reset_kernel<<<1, 64>>>();
    cudaEventRecord(eR, 0);
    prep_wxA_kernel<<<PREPA_BLOCKS, 256>>>(x, (__half*)pxq, (float*)pxs,
                                           w, ws, (__half*)pwd);

    // side: quant remaining x rows concurrently (gated on counter reset only)
    cudaStreamWaitEvent(cudaStreamPerThread, eR, 0);
    quant_x_side_kernel<<<SIDE_ROWS, 256, 0, cudaStreamPerThread>>>(
        x, (__half*)pxq, (float*)pxs);
    cudaEventRecord(eJ, cudaStreamPerThread);

    // main: single full GEMM launch; mtile>=PRE_MT CTAs gate on device flags
    gemm_kernel<<<(T_MAX / BM) * (O_DIM / BN), 256, SMEM_BYTES>>>(
        out, (float*)pxs, (const __half*)pxq, (const __half*)pwd, x);

    // rejoin side branch into the captured origin stream
    cudaStreamWaitEvent(0, eJ, 0);
}